// round 4
// baseline (speedup 1.0000x reference)
#include <cuda_runtime.h>
#include <cuda_bf16.h>

// GHMC loss, fully fused single kernel.
// loss = (1/n_nonempty) * sum_b ( bce_sum[b] / count[b] )
// per element: z = sigmoid(x); g = t ? 1-z : z; b = min((int)(g*10), 9);
//              bce = softplus(z) - t*z   (softplus via degree-5 poly on [0,1])
//
// Determinism: per-block partials reduced in fixed order, combined via integer
// (fixed-point 2^-18) u64 atomics (associative -> order-independent). The last
// block (fence+ticket) computes the loss once, writes out, and resets all
// global state so every graph replay starts identically.

#define BINS 10
#define THREADS 256
#define GRID 1184                 // 148 SMs * 8 blocks
#define FIX_SCALE 262144.0f      // 2^18
#define PACK_SHIFT 25            // bits [0,25): bce fix-point; [25,32): count
#define PACK_MASK  ((1u << PACK_SHIFT) - 1u)

__device__ unsigned long long g_bin_sum[BINS];   // fixed-point 2^-18
__device__ unsigned long long g_bin_cnt[BINS];
__device__ unsigned int       g_ticket;

__global__ __launch_bounds__(THREADS, 8)
void ghmc_fused_kernel(const float4* __restrict__ pred4,
                       const int4*   __restrict__ tgt4,
                       int nvec,
                       const float*  __restrict__ pred,
                       const int*    __restrict__ tgt,
                       int ntotal,
                       float* __restrict__ out)
{
    // One u32 per (bin, thread): packed {count:7, bce_fix:25}. Layout
    // [bin][tid] -> bank = tid%32: conflict-free RMW, no atomics in hot loop.
    __shared__ unsigned int s_pack[BINS * THREADS];

    const int tid = threadIdx.x;
#pragma unroll
    for (int b = 0; b < BINS; ++b)
        s_pack[b * THREADS + tid] = 0u;
    __syncthreads();

    const int stride = GRID * THREADS;

    // softplus(z) on z in [0,1]: Taylor about 0.5, max abs err ~4e-6.
    auto process = [&](float x, int t) {
        float u = __expf(-x);
        float z = __fdividef(1.0f, 1.0f + u);       // sigmoid(x)
        float g = t ? (1.0f - z) : z;               // |z - t|, t in {0,1}
        int   b = (int)(g * 10.0f);
        b = b > (BINS - 1) ? (BINS - 1) : b;
        float c  = z - 0.5f;
        float sp = 0.00087297f;
        sp = fmaf(sp, c, -0.00401487f);
        sp = fmaf(sp, c, -0.00959280f);
        sp = fmaf(sp, c,  0.11750186f);
        sp = fmaf(sp, c,  0.62245933f);
        sp = fmaf(sp, c,  0.97407699f);             // softplus(z)
        float bce = t ? (sp - z) : sp;              // softplus(z) - t*z >= 0
        unsigned int add = __float2uint_rn(bce * FIX_SCALE) + (1u << PACK_SHIFT);
        s_pack[b * THREADS + tid] += add;           // single smem RMW
    };

    for (int i = blockIdx.x * THREADS + tid; i < nvec; i += stride) {
        float4 p = pred4[i];
        int4   t = tgt4[i];
        process(p.x, t.x);
        process(p.y, t.y);
        process(p.z, t.z);
        process(p.w, t.w);
    }
    if (blockIdx.x == 0) {                          // scalar tail
        for (int i = nvec * 4 + tid; i < ntotal; i += THREADS)
            process(pred[i], tgt[i]);
    }

    __syncthreads();

    // Block reduction: warp w handles bins w, w+8 (fixed order), then one
    // u64 integer atomic per bin -> order-independent global result.
    const int wid  = tid >> 5;
    const int lane = tid & 31;
    for (int b = wid; b < BINS; b += 8) {
        unsigned long long s = 0ull;
        unsigned int       c = 0u;
#pragma unroll
        for (int i = lane; i < THREADS; i += 32) {
            unsigned int v = s_pack[b * THREADS + i];
            s += (unsigned long long)(v & PACK_MASK);
            c += (v >> PACK_SHIFT);
        }
#pragma unroll
        for (int off = 16; off; off >>= 1) {
            s += __shfl_down_sync(0xffffffffu, s, off);
            c += __shfl_down_sync(0xffffffffu, c, off);
        }
        if (lane == 0) {
            atomicAdd(&g_bin_sum[b], s);
            atomicAdd(&g_bin_cnt[b], (unsigned long long)c);
        }
    }

    // Fence + ticket: last block to arrive finalizes.
    __threadfence();
    __syncthreads();
    if (tid == 0) {
        unsigned int ticket = atomicAdd(&g_ticket, 1u);
        if (ticket == GRID - 1) {
            double loss = 0.0;
            int    n_ne = 0;
#pragma unroll
            for (int b = 0; b < BINS; ++b) {
                unsigned long long cb = atomicAdd(&g_bin_cnt[b], 0ull);
                unsigned long long sb = atomicAdd(&g_bin_sum[b], 0ull);
                if (cb > 0ull) {
                    ++n_ne;
                    loss += ((double)sb / (double)FIX_SCALE) / (double)cb;
                }
            }
            if (n_ne < 1) n_ne = 1;
            out[0] = (float)(loss / (double)n_ne);
            // Reset for next execution (graph replay / re-validation).
#pragma unroll
            for (int b = 0; b < BINS; ++b) {
                g_bin_sum[b] = 0ull;
                g_bin_cnt[b] = 0ull;
            }
            g_ticket = 0u;
            __threadfence();
        }
    }
}

extern "C" void kernel_launch(void* const* d_in, const int* in_sizes, int n_in,
                              void* d_out, int out_size)
{
    const float* pred = (const float*)d_in[0];
    const int*   tgt  = (const int*)d_in[1];
    float*       out  = (float*)d_out;
    const int n    = in_sizes[0];
    const int nvec = n >> 2;

    ghmc_fused_kernel<<<GRID, THREADS>>>((const float4*)pred, (const int4*)tgt,
                                         nvec, pred, tgt, n, out);
}

// round 5
// speedup vs baseline: 1.2168x; 1.2168x over previous
#include <cuda_runtime.h>
#include <cuda_bf16.h>

// GHMC loss, fully fused single kernel, warp-parallel finalize.
// loss = (1/n_nonempty) * sum_b ( bce_sum[b] / count[b] )
// per element: z = sigmoid(x); g = |z - t|; b = min((int)(g*10), 9);
//              bce = softplus(z) - t*z   (softplus via degree-5 poly on [0,1])
//
// Determinism: per-block partials reduced in fixed order, combined via integer
// (fixed-point 2^-18) u64 atomics (order-independent). Last block (ticket)
// finalizes with one warp in parallel, then resets all globals for the next
// graph replay.

#define BINS 10
#define THREADS 256
#define GRID 1184                 // 148 SMs * 8 blocks
#define FIX_SCALE 262144.0f       // 2^18
#define PACK_BIAS 33554432.0f     // 2^25
#define PACK_SHIFT 25             // bits [0,25): bce fix; [25,32): count
#define PACK_MASK  ((1u << PACK_SHIFT) - 1u)

__device__ unsigned long long g_bin_sum[BINS];   // fixed-point 2^-18
__device__ unsigned long long g_bin_cnt[BINS];
__device__ unsigned int       g_ticket;

__global__ __launch_bounds__(THREADS, 8)
void ghmc_fused_kernel(const float4* __restrict__ pred4,
                       const int4*   __restrict__ tgt4,
                       int nvec,
                       const float*  __restrict__ pred,
                       const int*    __restrict__ tgt,
                       int ntotal,
                       float* __restrict__ out)
{
    // One u32 per (bin, thread): packed {count:7, bce_fix:25}. Layout
    // [bin][tid] -> bank = tid%32: conflict-free RMW, no atomics in hot loop.
    __shared__ unsigned int s_pack[BINS * THREADS];

    const int tid = threadIdx.x;
#pragma unroll
    for (int b = 0; b < BINS; ++b)
        s_pack[b * THREADS + tid] = 0u;
    __syncthreads();

    const int stride = GRID * THREADS;

    // softplus(z), z in [0,1]: Taylor about 0.5, max abs err ~4e-6.
    auto process = [&](float x, int t) {
        float tf = (float)t;                        // t in {0,1}
        float u  = __expf(-x);
        float z  = __fdividef(1.0f, 1.0f + u);      // sigmoid(x)
        float g  = fabsf(z - tf);
        int   b  = (int)(g * 10.0f);
        b = b > (BINS - 1) ? (BINS - 1) : b;
        float c  = z - 0.5f;
        float sp = 0.00087297f;
        sp = fmaf(sp, c, -0.00401487f);
        sp = fmaf(sp, c, -0.00959280f);
        sp = fmaf(sp, c,  0.11750186f);
        sp = fmaf(sp, c,  0.62245933f);
        sp = fmaf(sp, c,  0.97407699f);             // softplus(z)
        float bce = fmaf(-tf, z, sp);               // softplus(z) - t*z >= 0
        // pack: count-increment folded into the FMA bias (2^25); low-field
        // rounding error < 4 ulp, never carries into the count bits.
        unsigned int add = __float2uint_rn(fmaf(bce, FIX_SCALE, PACK_BIAS));
        s_pack[b * THREADS + tid] += add;           // single smem RMW
    };

#pragma unroll 2
    for (int i = blockIdx.x * THREADS + tid; i < nvec; i += stride) {
        float4 p = pred4[i];
        int4   t = tgt4[i];
        process(p.x, t.x);
        process(p.y, t.y);
        process(p.z, t.z);
        process(p.w, t.w);
    }
    if (blockIdx.x == 0) {                          // scalar tail
        for (int i = nvec * 4 + tid; i < ntotal; i += THREADS)
            process(pred[i], tgt[i]);
    }

    __syncthreads();

    // Block reduction: warp w handles bins w, w+8 (fixed order), then one
    // u64 integer atomic per bin -> order-independent global result.
    const int wid  = tid >> 5;
    const int lane = tid & 31;
    for (int b = wid; b < BINS; b += 8) {
        unsigned long long s = 0ull;
        unsigned int       c = 0u;
#pragma unroll
        for (int i = lane; i < THREADS; i += 32) {
            unsigned int v = s_pack[b * THREADS + i];
            s += (unsigned long long)(v & PACK_MASK);
            c += (v >> PACK_SHIFT);
        }
#pragma unroll
        for (int off = 16; off; off >>= 1) {
            s += __shfl_down_sync(0xffffffffu, s, off);
            c += __shfl_down_sync(0xffffffffu, c, off);
        }
        if (lane == 0) {
            atomicAdd(&g_bin_sum[b], s);
            atomicAdd(&g_bin_cnt[b], (unsigned long long)c);
        }
    }

    // Every thread fences its own prior atomics, then the block syncs, so the
    // ticket increment is ordered after all of this block's bin atomics.
    __threadfence();
    __syncthreads();

    if (wid == 0) {
        unsigned int ticket = 0u;
        if (lane == 0) ticket = atomicAdd(&g_ticket, 1u);
        ticket = __shfl_sync(0xffffffffu, ticket, 0);
        if (ticket == GRID - 1) {
            // Warp-parallel finalize: lane b owns bin b. One LDG round-trip
            // and one warp-wide DDIV sequence instead of 20 serial atomics
            // and 10 serial divides.
            double ratio = 0.0;
            int    ne    = 0;
            unsigned long long s = 0ull, c = 0ull;
            if (lane < BINS) {
                c = *(volatile unsigned long long*)&g_bin_cnt[lane];
                s = *(volatile unsigned long long*)&g_bin_sum[lane];
                if (c > 0ull) {
                    ne    = 1;
                    ratio = (double)s / ((double)FIX_SCALE * (double)c);
                }
            }
#pragma unroll
            for (int off = 16; off; off >>= 1) {
                ratio += __shfl_down_sync(0xffffffffu, ratio, off);
                ne    += __shfl_down_sync(0xffffffffu, ne, off);
            }
            if (lane == 0) {
                if (ne < 1) ne = 1;
                out[0] = (float)(ratio / (double)ne);
            }
            // Reset for next execution; kernel-boundary ordering makes these
            // visible to the next launch.
            if (lane < BINS) {
                g_bin_sum[lane] = 0ull;
                g_bin_cnt[lane] = 0ull;
            }
            if (lane == 0) g_ticket = 0u;
        }
    }
}

extern "C" void kernel_launch(void* const* d_in, const int* in_sizes, int n_in,
                              void* d_out, int out_size)
{
    const float* pred = (const float*)d_in[0];
    const int*   tgt  = (const int*)d_in[1];
    float*       out  = (float*)d_out;
    const int n    = in_sizes[0];
    const int nvec = n >> 2;

    ghmc_fused_kernel<<<GRID, THREADS>>>((const float4*)pred, (const int4*)tgt,
                                         nvec, pred, tgt, n, out);
}